// round 2
// baseline (speedup 1.0000x reference)
#include <cuda_runtime.h>
#include <math.h>

// Problem constants
#define SEQ   2048
#define DMOD  1024
#define NHEAD 16
#define HDIM  64
#define DMLP  8192

// ---------------- scratch (static device globals; no allocation) -------------
__device__ float g_xn  [SEQ * DMOD];        //  8 MB
__device__ float g_qkv [SEQ * 3 * DMOD];    // 24 MB
__device__ float g_attn[SEQ * DMOD];        //  8 MB
__device__ float g_h   [SEQ * DMOD];        //  8 MB
__device__ float g_hn  [SEQ * DMOD];        //  8 MB
__device__ float g_g   [SEQ * DMLP];        // 64 MB
__device__ float g_mlp [SEQ * (DMLP/2)];    // 32 MB

// ---------------- LayerNorm: one block per row, D=1024 -----------------------
__global__ void __launch_bounds__(256) ln_kernel(const float* __restrict__ x,
                                                 float* __restrict__ y) {
    __shared__ float row[DMOD];
    __shared__ float red[256];
    const int r   = blockIdx.x;
    const int tid = threadIdx.x;
    const float* xr = x + (long)r * DMOD;

    float s = 0.f;
    #pragma unroll
    for (int i = 0; i < 4; i++) {
        float v = xr[tid + i * 256];
        row[tid + i * 256] = v;
        s += v;
    }
    red[tid] = s; __syncthreads();
    #pragma unroll
    for (int off = 128; off > 0; off >>= 1) {
        if (tid < off) red[tid] += red[tid + off];
        __syncthreads();
    }
    const float mu = red[0] * (1.f / DMOD);
    __syncthreads();

    float ss = 0.f;
    #pragma unroll
    for (int i = 0; i < 4; i++) {
        float d = row[tid + i * 256] - mu;
        ss += d * d;
    }
    red[tid] = ss; __syncthreads();
    #pragma unroll
    for (int off = 128; off > 0; off >>= 1) {
        if (tid < off) red[tid] += red[tid + off];
        __syncthreads();
    }
    const float inv = rsqrtf(red[0] * (1.f / DMOD) + 1e-5f);

    float* yr = y + (long)r * DMOD;
    #pragma unroll
    for (int i = 0; i < 4; i++) {
        int c = tid + i * 256;
        yr[c] = (row[c] - mu) * inv;
    }
}

// ---------------- SGEMM: C[M,N] = A[M,K] * B[N,K]^T (+ residual) -------------
// 128x128 tile, BK=8, 256 threads, 8x8 micro-tile per thread.
__global__ void __launch_bounds__(256) sgemm_nt(
    const float* __restrict__ A, int lda,
    const float* __restrict__ B, int ldb,
    float*       __restrict__ C, int ldc,
    const float* __restrict__ Res,   // nullable, same ld as C
    int K)
{
    __shared__ float As[8][128];
    __shared__ float Bs[8][128];

    const int tid = threadIdx.x;
    const int m0  = blockIdx.y * 128;
    const int n0  = blockIdx.x * 128;

    const int lr = tid >> 1;        // 0..127 : tile row being loaded
    const int lc = (tid & 1) * 4;   // 0 or 4 : k-quad being loaded

    const float* Ap = A + (long)(m0 + lr) * lda + lc;
    const float* Bp = B + (long)(n0 + lr) * ldb + lc;

    const int ty = tid >> 4;        // 0..15
    const int tx = tid & 15;        // 0..15

    float acc[8][8];
    #pragma unroll
    for (int i = 0; i < 8; i++)
        #pragma unroll
        for (int j = 0; j < 8; j++) acc[i][j] = 0.f;

    for (int k0 = 0; k0 < K; k0 += 8) {
        float4 av = *(const float4*)(Ap + k0);
        float4 bv = *(const float4*)(Bp + k0);
        As[lc + 0][lr] = av.x; As[lc + 1][lr] = av.y;
        As[lc + 2][lr] = av.z; As[lc + 3][lr] = av.w;
        Bs[lc + 0][lr] = bv.x; Bs[lc + 1][lr] = bv.y;
        Bs[lc + 2][lr] = bv.z; Bs[lc + 3][lr] = bv.w;
        __syncthreads();

        #pragma unroll
        for (int k = 0; k < 8; k++) {
            float a[8], b[8];
            #pragma unroll
            for (int i = 0; i < 8; i++) a[i] = As[k][ty * 8 + i];
            #pragma unroll
            for (int j = 0; j < 8; j++) b[j] = Bs[k][tx * 8 + j];
            #pragma unroll
            for (int i = 0; i < 8; i++)
                #pragma unroll
                for (int j = 0; j < 8; j++)
                    acc[i][j] += a[i] * b[j];
        }
        __syncthreads();
    }

    #pragma unroll
    for (int i = 0; i < 8; i++) {
        const long row = m0 + ty * 8 + i;
        float* Crow = C + row * (long)ldc + n0 + tx * 8;
        if (Res) {
            const float* Rrow = Res + row * (long)ldc + n0 + tx * 8;
            #pragma unroll
            for (int j = 0; j < 8; j++) Crow[j] = acc[i][j] + Rrow[j];
        } else {
            #pragma unroll
            for (int j = 0; j < 8; j++) Crow[j] = acc[i][j];
        }
    }
}

// ---------------- RoPE in-place on q and k of the qkv buffer -----------------
__global__ void rope_kernel(float* __restrict__ qkv) {
    const int idx = blockIdx.x * 256 + threadIdx.x;  // over SEQ*NHEAD*32
    if (idx >= SEQ * NHEAD * 32) return;
    const int j = idx & 31;
    const int h = (idx >> 5) & (NHEAD - 1);
    const int l = idx >> 9;

    const float inv_freq = powf(10000.f, -(float)j / 32.f);
    const float ang = (float)l * inv_freq;
    float c, s;
    sincosf(ang, &s, &c);   // FIXED: sincosf(x, sin_ptr, cos_ptr)

    float* qp = qkv + (long)l * (3 * DMOD) + h * HDIM + j;
    float q1 = qp[0], q2 = qp[32];
    qp[0]  = q1 * c - q2 * s;
    qp[32] = q2 * c + q1 * s;

    float* kp = qp + DMOD;
    float k1 = kp[0], k2 = kp[32];
    kp[0]  = k1 * c - k2 * s;
    kp[32] = k2 * c + k1 * s;
}

// ---------------- Flash attention: causal, 64x64 tiles -----------------------
// grid = (NHEAD, SEQ/64). 256 threads: thread t -> row r=t/4, col segment
// (t%4)*16..+15. Padded smem stride 68 keeps float4 alignment.
#define AT_STRIDE 68
#define AT_SMEM   (4 * 64 * AT_STRIDE * 4)

__global__ void __launch_bounds__(256) attn_kernel(const float* __restrict__ qkv,
                                                   float* __restrict__ out) {
    extern __shared__ float sm[];
    float* Qs = sm;
    float* Ks = Qs + 64 * AT_STRIDE;
    float* Vs = Ks + 64 * AT_STRIDE;
    float* Ss = Vs + 64 * AT_STRIDE;

    const int h   = blockIdx.x;
    const int qb  = blockIdx.y;
    const int tid = threadIdx.x;
    const int r   = tid >> 2;
    const int cs  = (tid & 3) * 16;
    const int qbase = qb * 64;
    const float scale = 0.125f;  // HD^-0.5

    // load Q (pre-scaled)
    #pragma unroll
    for (int it = 0; it < 16; it++) {
        int idx = tid + it * 256;
        int row = idx >> 6, col = idx & 63;
        Qs[row * AT_STRIDE + col] =
            qkv[(long)(qbase + row) * (3 * DMOD) + h * HDIM + col] * scale;
    }

    float m = -1e30f, lsum = 0.f;
    float o[16];
    #pragma unroll
    for (int j = 0; j < 16; j++) o[j] = 0.f;

    for (int kb = 0; kb <= qb; kb++) {
        const int kbase = kb * 64;
        #pragma unroll
        for (int it = 0; it < 16; it++) {
            int idx = tid + it * 256;
            int row = idx >> 6, col = idx & 63;
            long base = (long)(kbase + row) * (3 * DMOD) + h * HDIM + col;
            Ks[row * AT_STRIDE + col] = qkv[base + DMOD];
            Vs[row * AT_STRIDE + col] = qkv[base + 2 * DMOD];
        }
        __syncthreads();

        // S = Q K^T for this thread's 16 columns
        float s[16];
        #pragma unroll
        for (int j = 0; j < 16; j++) s[j] = 0.f;
        #pragma unroll
        for (int d0 = 0; d0 < 64; d0 += 4) {
            float4 q4 = *(const float4*)(Qs + r * AT_STRIDE + d0);
            #pragma unroll
            for (int j = 0; j < 16; j++) {
                float4 k4 = *(const float4*)(Ks + (cs + j) * AT_STRIDE + d0);
                s[j] += q4.x * k4.x + q4.y * k4.y + q4.z * k4.z + q4.w * k4.w;
            }
        }

        if (kb == qb) {  // causal mask on the diagonal block
            #pragma unroll
            for (int j = 0; j < 16; j++)
                if (kbase + cs + j > qbase + r) s[j] = -1e30f;
        }

        // online softmax
        float mloc = s[0];
        #pragma unroll
        for (int j = 1; j < 16; j++) mloc = fmaxf(mloc, s[j]);
        mloc = fmaxf(mloc, __shfl_xor_sync(0xffffffffu, mloc, 1));
        mloc = fmaxf(mloc, __shfl_xor_sync(0xffffffffu, mloc, 2));
        const float mnew  = fmaxf(m, mloc);
        const float alpha = __expf(m - mnew);

        float ps = 0.f;
        #pragma unroll
        for (int j = 0; j < 16; j++) {
            float p = __expf(s[j] - mnew);
            ps += p;
            Ss[r * AT_STRIDE + cs + j] = p;
        }
        ps += __shfl_xor_sync(0xffffffffu, ps, 1);
        ps += __shfl_xor_sync(0xffffffffu, ps, 2);
        lsum = lsum * alpha + ps;
        m = mnew;
        #pragma unroll
        for (int j = 0; j < 16; j++) o[j] *= alpha;
        __syncthreads();  // Ss fully written

        // O += P V
        #pragma unroll 4
        for (int c = 0; c < 64; c++) {
            float p = Ss[r * AT_STRIDE + c];
            #pragma unroll
            for (int jj = 0; jj < 4; jj++) {
                float4 v = *(const float4*)(Vs + c * AT_STRIDE + cs + jj * 4);
                o[jj * 4 + 0] += p * v.x;
                o[jj * 4 + 1] += p * v.y;
                o[jj * 4 + 2] += p * v.z;
                o[jj * 4 + 3] += p * v.w;
            }
        }
        __syncthreads();  // done with K/V/Ss before next tile load
    }

    const float invl = 1.f / lsum;
    float* orow = out + (long)(qbase + r) * DMOD + h * HDIM + cs;
    #pragma unroll
    for (int j = 0; j < 16; j++) orow[j] = o[j] * invl;
}

// ---------------- SwiGLU: mlp = silu(g[:,4096:]) * g[:,:4096] ----------------
__global__ void swiglu_kernel(const float* __restrict__ g,
                              float* __restrict__ out) {
    const int idx = blockIdx.x * 256 + threadIdx.x;
    if (idx >= SEQ * (DMLP / 2)) return;
    const int rw = idx >> 12;          // /4096
    const int c  = idx & 4095;
    const float x1 = g[(long)rw * DMLP + c];
    const float x2 = g[(long)rw * DMLP + (DMLP / 2) + c];
    const float sig = 1.f / (1.f + __expf(-x2));
    out[idx] = x2 * sig * x1;
}

// ---------------- launch ------------------------------------------------------
extern "C" void kernel_launch(void* const* d_in, const int* in_sizes, int n_in,
                              void* d_out, int out_size) {
    const float* x      = (const float*)d_in[0];
    // d_in[1] = mask: exactly causal tril -> handled analytically in attn_kernel
    const float* W_attn = (const float*)d_in[2];
    const float* W_out  = (const float*)d_in[3];
    const float* W_ffp  = (const float*)d_in[4];
    const float* W_ffo  = (const float*)d_in[5];
    float* out = (float*)d_out;

    float *xn, *qkv, *attn, *h, *hn, *gbuf, *mlp;
    cudaGetSymbolAddress((void**)&xn,   g_xn);
    cudaGetSymbolAddress((void**)&qkv,  g_qkv);
    cudaGetSymbolAddress((void**)&attn, g_attn);
    cudaGetSymbolAddress((void**)&h,    g_h);
    cudaGetSymbolAddress((void**)&hn,   g_hn);
    cudaGetSymbolAddress((void**)&gbuf, g_g);
    cudaGetSymbolAddress((void**)&mlp,  g_mlp);

    cudaFuncSetAttribute(attn_kernel,
                         cudaFuncAttributeMaxDynamicSharedMemorySize, AT_SMEM);

    // 1) xn = LN(x)
    ln_kernel<<<SEQ, 256>>>(x, xn);

    // 2) qkv = xn @ W_attn^T   [2048,3072]
    sgemm_nt<<<dim3(3 * DMOD / 128, SEQ / 128), 256>>>(
        xn, DMOD, W_attn, DMOD, qkv, 3 * DMOD, nullptr, DMOD);

    // 3) RoPE on q,k in place
    rope_kernel<<<(SEQ * NHEAD * 32 + 255) / 256, 256>>>(qkv);

    // 4) causal flash attention -> attn [2048,1024] (head-interleaved layout)
    attn_kernel<<<dim3(NHEAD, SEQ / 64), 256, AT_SMEM>>>(qkv, attn);

    // 5) h = attn @ W_out^T + x
    sgemm_nt<<<dim3(DMOD / 128, SEQ / 128), 256>>>(
        attn, DMOD, W_out, DMOD, h, DMOD, x, DMOD);

    // 6) hn = LN(h)
    ln_kernel<<<SEQ, 256>>>(h, hn);

    // 7) g = hn @ W_ffp^T   [2048,8192]
    sgemm_nt<<<dim3(DMLP / 128, SEQ / 128), 256>>>(
        hn, DMOD, W_ffp, DMOD, gbuf, DMLP, nullptr, DMOD);

    // 8) mlp = silu(g2) * g1   [2048,4096]
    swiglu_kernel<<<(SEQ * (DMLP / 2) + 255) / 256, 256>>>(gbuf, mlp);

    // 9) out = mlp @ W_ffo^T + h
    sgemm_nt<<<dim3(DMOD / 128, SEQ / 128), 256>>>(
        mlp, DMLP / 2, W_ffo, DMLP / 2, out, DMOD, h, DMLP / 2);
}

// round 3
// speedup vs baseline: 1.2218x; 1.2218x over previous
#include <cuda_runtime.h>
#include <cuda_bf16.h>
#include <mma.h>
#include <math.h>

using namespace nvcuda;

// Problem constants
#define SEQ   2048
#define DMOD  1024
#define NHEAD 16
#define HDIM  64
#define DMLP  8192

// ---------------- scratch (static device globals; no allocation) -------------
__device__ float g_xn  [SEQ * DMOD];        //  8 MB
__device__ float g_qkv [SEQ * 3 * DMOD];    // 24 MB
__device__ float g_attn[SEQ * DMOD];        //  8 MB
__device__ float g_h   [SEQ * DMOD];        //  8 MB
__device__ float g_hn  [SEQ * DMOD];        //  8 MB
__device__ float g_g   [SEQ * DMLP];        // 64 MB
__device__ float g_mlp [SEQ * (DMLP/2)];    // 32 MB

// ---------------- LayerNorm: one block per row, D=1024 -----------------------
__global__ void __launch_bounds__(256) ln_kernel(const float* __restrict__ x,
                                                 float* __restrict__ y) {
    __shared__ float row[DMOD];
    __shared__ float red[256];
    const int r   = blockIdx.x;
    const int tid = threadIdx.x;
    const float* xr = x + (long)r * DMOD;

    float s = 0.f;
    #pragma unroll
    for (int i = 0; i < 4; i++) {
        float v = xr[tid + i * 256];
        row[tid + i * 256] = v;
        s += v;
    }
    red[tid] = s; __syncthreads();
    #pragma unroll
    for (int off = 128; off > 0; off >>= 1) {
        if (tid < off) red[tid] += red[tid + off];
        __syncthreads();
    }
    const float mu = red[0] * (1.f / DMOD);
    __syncthreads();

    float ss = 0.f;
    #pragma unroll
    for (int i = 0; i < 4; i++) {
        float d = row[tid + i * 256] - mu;
        ss += d * d;
    }
    red[tid] = ss; __syncthreads();
    #pragma unroll
    for (int off = 128; off > 0; off >>= 1) {
        if (tid < off) red[tid] += red[tid + off];
        __syncthreads();
    }
    const float inv = rsqrtf(red[0] * (1.f / DMOD) + 1e-5f);

    float* yr = y + (long)r * DMOD;
    #pragma unroll
    for (int i = 0; i < 4; i++) {
        int c = tid + i * 256;
        yr[c] = (row[c] - mu) * inv;
    }
}

// ---------------- Tensor-core GEMM: C[M,N] = A[M,K] * B[N,K]^T (+Res) --------
// bf16 split-precision (hi/lo): C = Ah*Bh + Ah*Bl + Al*Bh, fp32 accumulate.
// 128x128 block tile, BK=32. 256 threads = 8 warps; warp tile 32x64
// (2x4 grid of 16x16 wmma tiles). Residual is preloaded into the accumulator
// fragments. All dims are multiples of 128/32 -> no bounds checks.
#define GBM 128
#define GBN 128
#define GBK 32

__global__ void __launch_bounds__(256) gemm_bf16x3(
    const float* __restrict__ A, int lda,
    const float* __restrict__ B, int ldb,
    float*       __restrict__ C, int ldc,
    const float* __restrict__ Res,   // nullable; leading dim = ldc
    int K)
{
    __shared__ __nv_bfloat16 Ah[GBM][GBK];
    __shared__ __nv_bfloat16 Al[GBM][GBK];
    __shared__ __nv_bfloat16 Bh[GBN][GBK];
    __shared__ __nv_bfloat16 Bl[GBN][GBK];

    const int tid = threadIdx.x;
    const int m0  = blockIdx.y * GBM;
    const int n0  = blockIdx.x * GBN;

    const int warp = tid >> 5;
    const int wm0  = (warp & 3) * 32;   // warp row offset in tile (0,32,64,96)
    const int wn0  = (warp >> 2) * 64;  // warp col offset in tile (0,64)

    wmma::fragment<wmma::accumulator, 16, 16, 16, float> acc[2][4];
    #pragma unroll
    for (int i = 0; i < 2; i++)
        #pragma unroll
        for (int j = 0; j < 4; j++) {
            if (Res) {
                const float* rp = Res + (long)(m0 + wm0 + 16 * i) * ldc
                                      + n0 + wn0 + 16 * j;
                wmma::load_matrix_sync(acc[i][j], rp, ldc, wmma::mem_row_major);
            } else {
                wmma::fill_fragment(acc[i][j], 0.f);
            }
        }

    // per-thread load mapping: 8 float4 per tile side
    // linear f4 index = tid + it*256; row = idx/8 (GBK=32 -> 8 f4/row)
    for (int k0 = 0; k0 < K; k0 += GBK) {
        #pragma unroll
        for (int it = 0; it < 4; it++) {
            int idx = tid + it * 256;
            int row = idx >> 3;
            int c4  = (idx & 7) * 4;
            float4 av = *(const float4*)(A + (long)(m0 + row) * lda + k0 + c4);
            float4 bv = *(const float4*)(B + (long)(n0 + row) * ldb + k0 + c4);
            float aa[4] = {av.x, av.y, av.z, av.w};
            float bb[4] = {bv.x, bv.y, bv.z, bv.w};
            #pragma unroll
            for (int e = 0; e < 4; e++) {
                __nv_bfloat16 h = __float2bfloat16(aa[e]);
                Ah[row][c4 + e] = h;
                Al[row][c4 + e] = __float2bfloat16(aa[e] - __bfloat162float(h));
                __nv_bfloat16 g = __float2bfloat16(bb[e]);
                Bh[row][c4 + e] = g;
                Bl[row][c4 + e] = __float2bfloat16(bb[e] - __bfloat162float(g));
            }
        }
        __syncthreads();

        #pragma unroll
        for (int ks = 0; ks < GBK; ks += 16) {
            wmma::fragment<wmma::matrix_a, 16, 16, 16, __nv_bfloat16,
                           wmma::row_major> ah[2], al[2];
            #pragma unroll
            for (int i = 0; i < 2; i++) {
                wmma::load_matrix_sync(ah[i], &Ah[wm0 + 16 * i][ks], GBK);
                wmma::load_matrix_sync(al[i], &Al[wm0 + 16 * i][ks], GBK);
            }
            #pragma unroll
            for (int j = 0; j < 4; j++) {
                wmma::fragment<wmma::matrix_b, 16, 16, 16, __nv_bfloat16,
                               wmma::col_major> bh, bl;
                wmma::load_matrix_sync(bh, &Bh[wn0 + 16 * j][ks], GBK);
                wmma::load_matrix_sync(bl, &Bl[wn0 + 16 * j][ks], GBK);
                #pragma unroll
                for (int i = 0; i < 2; i++) {
                    wmma::mma_sync(acc[i][j], ah[i], bl, acc[i][j]);
                    wmma::mma_sync(acc[i][j], al[i], bh, acc[i][j]);
                    wmma::mma_sync(acc[i][j], ah[i], bh, acc[i][j]);
                }
            }
        }
        __syncthreads();
    }

    #pragma unroll
    for (int i = 0; i < 2; i++)
        #pragma unroll
        for (int j = 0; j < 4; j++) {
            float* cp = C + (long)(m0 + wm0 + 16 * i) * ldc + n0 + wn0 + 16 * j;
            wmma::store_matrix_sync(cp, acc[i][j], ldc, wmma::mem_row_major);
        }
}

// ---------------- RoPE in-place on q and k of the qkv buffer -----------------
__global__ void rope_kernel(float* __restrict__ qkv) {
    const int idx = blockIdx.x * 256 + threadIdx.x;  // over SEQ*NHEAD*32
    if (idx >= SEQ * NHEAD * 32) return;
    const int j = idx & 31;
    const int h = (idx >> 5) & (NHEAD - 1);
    const int l = idx >> 9;

    const float inv_freq = powf(10000.f, -(float)j / 32.f);
    const float ang = (float)l * inv_freq;
    float c, s;
    sincosf(ang, &s, &c);

    float* qp = qkv + (long)l * (3 * DMOD) + h * HDIM + j;
    float q1 = qp[0], q2 = qp[32];
    qp[0]  = q1 * c - q2 * s;
    qp[32] = q2 * c + q1 * s;

    float* kp = qp + DMOD;
    float k1 = kp[0], k2 = kp[32];
    kp[0]  = k1 * c - k2 * s;
    kp[32] = k2 * c + k1 * s;
}

// ---------------- Flash attention: causal, 64x64 tiles (fp32) ----------------
#define AT_STRIDE 68
#define AT_SMEM   (4 * 64 * AT_STRIDE * 4)

__global__ void __launch_bounds__(256) attn_kernel(const float* __restrict__ qkv,
                                                   float* __restrict__ out) {
    extern __shared__ float sm[];
    float* Qs = sm;
    float* Ks = Qs + 64 * AT_STRIDE;
    float* Vs = Ks + 64 * AT_STRIDE;
    float* Ss = Vs + 64 * AT_STRIDE;

    const int h   = blockIdx.x;
    const int qb  = blockIdx.y;
    const int tid = threadIdx.x;
    const int r   = tid >> 2;
    const int cs  = (tid & 3) * 16;
    const int qbase = qb * 64;
    const float scale = 0.125f;  // HD^-0.5

    #pragma unroll
    for (int it = 0; it < 16; it++) {
        int idx = tid + it * 256;
        int row = idx >> 6, col = idx & 63;
        Qs[row * AT_STRIDE + col] =
            qkv[(long)(qbase + row) * (3 * DMOD) + h * HDIM + col] * scale;
    }

    float m = -1e30f, lsum = 0.f;
    float o[16];
    #pragma unroll
    for (int j = 0; j < 16; j++) o[j] = 0.f;

    for (int kb = 0; kb <= qb; kb++) {
        const int kbase = kb * 64;
        #pragma unroll
        for (int it = 0; it < 16; it++) {
            int idx = tid + it * 256;
            int row = idx >> 6, col = idx & 63;
            long base = (long)(kbase + row) * (3 * DMOD) + h * HDIM + col;
            Ks[row * AT_STRIDE + col] = qkv[base + DMOD];
            Vs[row * AT_STRIDE + col] = qkv[base + 2 * DMOD];
        }
        __syncthreads();

        float s[16];
        #pragma unroll
        for (int j = 0; j < 16; j++) s[j] = 0.f;
        #pragma unroll
        for (int d0 = 0; d0 < 64; d0 += 4) {
            float4 q4 = *(const float4*)(Qs + r * AT_STRIDE + d0);
            #pragma unroll
            for (int j = 0; j < 16; j++) {
                float4 k4 = *(const float4*)(Ks + (cs + j) * AT_STRIDE + d0);
                s[j] += q4.x * k4.x + q4.y * k4.y + q4.z * k4.z + q4.w * k4.w;
            }
        }

        if (kb == qb) {
            #pragma unroll
            for (int j = 0; j < 16; j++)
                if (kbase + cs + j > qbase + r) s[j] = -1e30f;
        }

        float mloc = s[0];
        #pragma unroll
        for (int j = 1; j < 16; j++) mloc = fmaxf(mloc, s[j]);
        mloc = fmaxf(mloc, __shfl_xor_sync(0xffffffffu, mloc, 1));
        mloc = fmaxf(mloc, __shfl_xor_sync(0xffffffffu, mloc, 2));
        const float mnew  = fmaxf(m, mloc);
        const float alpha = __expf(m - mnew);

        float ps = 0.f;
        #pragma unroll
        for (int j = 0; j < 16; j++) {
            float p = __expf(s[j] - mnew);
            ps += p;
            Ss[r * AT_STRIDE + cs + j] = p;
        }
        ps += __shfl_xor_sync(0xffffffffu, ps, 1);
        ps += __shfl_xor_sync(0xffffffffu, ps, 2);
        lsum = lsum * alpha + ps;
        m = mnew;
        #pragma unroll
        for (int j = 0; j < 16; j++) o[j] *= alpha;
        __syncthreads();

        #pragma unroll 4
        for (int c = 0; c < 64; c++) {
            float p = Ss[r * AT_STRIDE + c];
            #pragma unroll
            for (int jj = 0; jj < 4; jj++) {
                float4 v = *(const float4*)(Vs + c * AT_STRIDE + cs + jj * 4);
                o[jj * 4 + 0] += p * v.x;
                o[jj * 4 + 1] += p * v.y;
                o[jj * 4 + 2] += p * v.z;
                o[jj * 4 + 3] += p * v.w;
            }
        }
        __syncthreads();
    }

    const float invl = 1.f / lsum;
    float* orow = out + (long)(qbase + r) * DMOD + h * HDIM + cs;
    #pragma unroll
    for (int j = 0; j < 16; j++) orow[j] = o[j] * invl;
}

// ---------------- SwiGLU: mlp = silu(g[:,4096:]) * g[:,:4096] ----------------
__global__ void swiglu_kernel(const float* __restrict__ g,
                              float* __restrict__ out) {
    const int idx = blockIdx.x * 256 + threadIdx.x;
    if (idx >= SEQ * (DMLP / 2)) return;
    const int rw = idx >> 12;
    const int c  = idx & 4095;
    const float x1 = g[(long)rw * DMLP + c];
    const float x2 = g[(long)rw * DMLP + (DMLP / 2) + c];
    const float sig = 1.f / (1.f + __expf(-x2));
    out[idx] = x2 * sig * x1;
}

// ---------------- launch ------------------------------------------------------
extern "C" void kernel_launch(void* const* d_in, const int* in_sizes, int n_in,
                              void* d_out, int out_size) {
    const float* x      = (const float*)d_in[0];
    // d_in[1] = mask: exactly causal tril -> handled analytically in attn_kernel
    const float* W_attn = (const float*)d_in[2];
    const float* W_out  = (const float*)d_in[3];
    const float* W_ffp  = (const float*)d_in[4];
    const float* W_ffo  = (const float*)d_in[5];
    float* out = (float*)d_out;

    float *xn, *qkv, *attn, *h, *hn, *gbuf, *mlp;
    cudaGetSymbolAddress((void**)&xn,   g_xn);
    cudaGetSymbolAddress((void**)&qkv,  g_qkv);
    cudaGetSymbolAddress((void**)&attn, g_attn);
    cudaGetSymbolAddress((void**)&h,    g_h);
    cudaGetSymbolAddress((void**)&hn,   g_hn);
    cudaGetSymbolAddress((void**)&gbuf, g_g);
    cudaGetSymbolAddress((void**)&mlp,  g_mlp);

    cudaFuncSetAttribute(attn_kernel,
                         cudaFuncAttributeMaxDynamicSharedMemorySize, AT_SMEM);

    // 1) xn = LN(x)
    ln_kernel<<<SEQ, 256>>>(x, xn);

    // 2) qkv = xn @ W_attn^T   [2048,3072]
    gemm_bf16x3<<<dim3(3 * DMOD / GBN, SEQ / GBM), 256>>>(
        xn, DMOD, W_attn, DMOD, qkv, 3 * DMOD, nullptr, DMOD);

    // 3) RoPE on q,k in place
    rope_kernel<<<(SEQ * NHEAD * 32 + 255) / 256, 256>>>(qkv);

    // 4) causal flash attention -> attn [2048,1024]
    attn_kernel<<<dim3(NHEAD, SEQ / 64), 256, AT_SMEM>>>(qkv, attn);

    // 5) h = attn @ W_out^T + x
    gemm_bf16x3<<<dim3(DMOD / GBN, SEQ / GBM), 256>>>(
        attn, DMOD, W_out, DMOD, h, DMOD, x, DMOD);

    // 6) hn = LN(h)
    ln_kernel<<<SEQ, 256>>>(h, hn);

    // 7) g = hn @ W_ffp^T   [2048,8192]
    gemm_bf16x3<<<dim3(DMLP / GBN, SEQ / GBM), 256>>>(
        hn, DMOD, W_ffp, DMOD, gbuf, DMLP, nullptr, DMOD);

    // 8) mlp = silu(g2) * g1   [2048,4096]
    swiglu_kernel<<<(SEQ * (DMLP / 2) + 255) / 256, 256>>>(gbuf, mlp);

    // 9) out = mlp @ W_ffo^T + h
    gemm_bf16x3<<<dim3(DMOD / GBN, SEQ / GBM), 256>>>(
        mlp, DMLP / 2, W_ffo, DMLP / 2, out, DMOD, h, DMLP / 2);
}

// round 4
// speedup vs baseline: 2.4803x; 2.0301x over previous
#include <cuda_runtime.h>
#include <cuda_bf16.h>
#include <mma.h>
#include <math.h>

using namespace nvcuda;

// Problem constants
#define SEQ   2048
#define DMOD  1024
#define NHEAD 16
#define HDIM  64
#define DMLP  8192

// ---------------- scratch (static device globals; no allocation) -------------
__device__ float g_xn  [SEQ * DMOD];
__device__ float g_qkv [SEQ * 3 * DMOD];
__device__ float g_attn[SEQ * DMOD];
__device__ float g_h   [SEQ * DMOD];
__device__ float g_hn  [SEQ * DMOD];
__device__ float g_g   [SEQ * DMLP];
__device__ float g_mlp [SEQ * (DMLP/2)];

// ---------------- LayerNorm ---------------------------------------------------
__global__ void __launch_bounds__(256) ln_kernel(const float* __restrict__ x,
                                                 float* __restrict__ y) {
    __shared__ float row[DMOD];
    __shared__ float red[256];
    const int r   = blockIdx.x;
    const int tid = threadIdx.x;
    const float* xr = x + (long)r * DMOD;

    float s = 0.f;
    #pragma unroll
    for (int i = 0; i < 4; i++) {
        float v = xr[tid + i * 256];
        row[tid + i * 256] = v;
        s += v;
    }
    red[tid] = s; __syncthreads();
    #pragma unroll
    for (int off = 128; off > 0; off >>= 1) {
        if (tid < off) red[tid] += red[tid + off];
        __syncthreads();
    }
    const float mu = red[0] * (1.f / DMOD);
    __syncthreads();

    float ss = 0.f;
    #pragma unroll
    for (int i = 0; i < 4; i++) {
        float d = row[tid + i * 256] - mu;
        ss += d * d;
    }
    red[tid] = ss; __syncthreads();
    #pragma unroll
    for (int off = 128; off > 0; off >>= 1) {
        if (tid < off) red[tid] += red[tid + off];
        __syncthreads();
    }
    const float inv = rsqrtf(red[0] * (1.f / DMOD) + 1e-5f);

    float* yr = y + (long)r * DMOD;
    #pragma unroll
    for (int i = 0; i < 4; i++) {
        int c = tid + i * 256;
        yr[c] = (row[c] - mu) * inv;
    }
}

// ---------------- Tensor-core GEMM with register prefetch --------------------
#define GBM 128
#define GBN 128
#define GBK 32

__global__ void __launch_bounds__(256) gemm_bf16x3(
    const float* __restrict__ A, int lda,
    const float* __restrict__ B, int ldb,
    float*       __restrict__ C, int ldc,
    const float* __restrict__ Res,
    int K)
{
    __shared__ __nv_bfloat16 Ah[GBM][GBK];
    __shared__ __nv_bfloat16 Al[GBM][GBK];
    __shared__ __nv_bfloat16 Bh[GBN][GBK];
    __shared__ __nv_bfloat16 Bl[GBN][GBK];

    const int tid = threadIdx.x;
    const int m0  = blockIdx.y * GBM;
    const int n0  = blockIdx.x * GBN;

    const int warp = tid >> 5;
    const int wm0  = (warp & 3) * 32;
    const int wn0  = (warp >> 2) * 64;

    wmma::fragment<wmma::accumulator, 16, 16, 16, float> acc[2][4];
    #pragma unroll
    for (int i = 0; i < 2; i++)
        #pragma unroll
        for (int j = 0; j < 4; j++) {
            if (Res) {
                const float* rp = Res + (long)(m0 + wm0 + 16 * i) * ldc
                                      + n0 + wn0 + 16 * j;
                wmma::load_matrix_sync(acc[i][j], rp, ldc, wmma::mem_row_major);
            } else {
                wmma::fill_fragment(acc[i][j], 0.f);
            }
        }

    // prefetch registers
    float4 av[4], bv[4];
    #pragma unroll
    for (int it = 0; it < 4; it++) {
        int idx = tid + it * 256;
        int row = idx >> 3;
        int c4  = (idx & 7) * 4;
        av[it] = *(const float4*)(A + (long)(m0 + row) * lda + c4);
        bv[it] = *(const float4*)(B + (long)(n0 + row) * ldb + c4);
    }

    for (int k0 = 0; k0 < K; k0 += GBK) {
        // store current prefetch to smem (hi/lo split)
        #pragma unroll
        for (int it = 0; it < 4; it++) {
            int idx = tid + it * 256;
            int row = idx >> 3;
            int c4  = (idx & 7) * 4;
            float aa[4] = {av[it].x, av[it].y, av[it].z, av[it].w};
            float bb[4] = {bv[it].x, bv[it].y, bv[it].z, bv[it].w};
            #pragma unroll
            for (int e = 0; e < 4; e++) {
                __nv_bfloat16 h = __float2bfloat16(aa[e]);
                Ah[row][c4 + e] = h;
                Al[row][c4 + e] = __float2bfloat16(aa[e] - __bfloat162float(h));
                __nv_bfloat16 g = __float2bfloat16(bb[e]);
                Bh[row][c4 + e] = g;
                Bl[row][c4 + e] = __float2bfloat16(bb[e] - __bfloat162float(g));
            }
        }
        __syncthreads();

        // issue next slab's loads (overlap with mma)
        if (k0 + GBK < K) {
            #pragma unroll
            for (int it = 0; it < 4; it++) {
                int idx = tid + it * 256;
                int row = idx >> 3;
                int c4  = (idx & 7) * 4;
                av[it] = *(const float4*)(A + (long)(m0 + row) * lda + k0 + GBK + c4);
                bv[it] = *(const float4*)(B + (long)(n0 + row) * ldb + k0 + GBK + c4);
            }
        }

        #pragma unroll
        for (int ks = 0; ks < GBK; ks += 16) {
            wmma::fragment<wmma::matrix_a, 16, 16, 16, __nv_bfloat16,
                           wmma::row_major> ah[2], al[2];
            #pragma unroll
            for (int i = 0; i < 2; i++) {
                wmma::load_matrix_sync(ah[i], &Ah[wm0 + 16 * i][ks], GBK);
                wmma::load_matrix_sync(al[i], &Al[wm0 + 16 * i][ks], GBK);
            }
            #pragma unroll
            for (int j = 0; j < 4; j++) {
                wmma::fragment<wmma::matrix_b, 16, 16, 16, __nv_bfloat16,
                               wmma::col_major> bh, bl;
                wmma::load_matrix_sync(bh, &Bh[wn0 + 16 * j][ks], GBK);
                wmma::load_matrix_sync(bl, &Bl[wn0 + 16 * j][ks], GBK);
                #pragma unroll
                for (int i = 0; i < 2; i++) {
                    wmma::mma_sync(acc[i][j], ah[i], bl, acc[i][j]);
                    wmma::mma_sync(acc[i][j], al[i], bh, acc[i][j]);
                    wmma::mma_sync(acc[i][j], ah[i], bh, acc[i][j]);
                }
            }
        }
        __syncthreads();
    }

    #pragma unroll
    for (int i = 0; i < 2; i++)
        #pragma unroll
        for (int j = 0; j < 4; j++) {
            float* cp = C + (long)(m0 + wm0 + 16 * i) * ldc + n0 + wn0 + 16 * j;
            wmma::store_matrix_sync(cp, acc[i][j], ldc, wmma::mem_row_major);
        }
}

// ---------------- RoPE --------------------------------------------------------
__global__ void rope_kernel(float* __restrict__ qkv) {
    const int idx = blockIdx.x * 256 + threadIdx.x;
    if (idx >= SEQ * NHEAD * 32) return;
    const int j = idx & 31;
    const int h = (idx >> 5) & (NHEAD - 1);
    const int l = idx >> 9;

    const float inv_freq = powf(10000.f, -(float)j / 32.f);
    const float ang = (float)l * inv_freq;
    float c, s;
    sincosf(ang, &s, &c);

    float* qp = qkv + (long)l * (3 * DMOD) + h * HDIM + j;
    float q1 = qp[0], q2 = qp[32];
    qp[0]  = q1 * c - q2 * s;
    qp[32] = q2 * c + q1 * s;

    float* kp = qp + DMOD;
    float k1 = kp[0], k2 = kp[32];
    kp[0]  = k1 * c - k2 * s;
    kp[32] = k2 * c + k1 * s;
}

// ---------------- Flash attention on tensor cores ----------------------------
// 64x64 tiles, split-precision wmma for both QK^T and PV.
// smem: Kh/Kl/Vh/Vl bf16 (stride 72), Sf (=T) and Of fp32 (stride 68).
// P aliases Kh/Kl. Q fragments live in registers.
#define BSTR 72
#define FSTR 68
#define ATW_SMEM (4 * 64 * BSTR * 2 + 2 * 64 * FSTR * 4)   // 71680 B

__global__ void __launch_bounds__(256, 2) attn_wmma(const float* __restrict__ qkv,
                                                    float* __restrict__ out) {
    extern __shared__ char smraw[];
    __nv_bfloat16* Kh = (__nv_bfloat16*)smraw;
    __nv_bfloat16* Kl = Kh + 64 * BSTR;
    __nv_bfloat16* Vh = Kl + 64 * BSTR;
    __nv_bfloat16* Vl = Vh + 64 * BSTR;
    float* Sf = (float*)(Vl + 64 * BSTR);   // S, later T
    float* Of = Sf + 64 * FSTR;
    __nv_bfloat16* Ph = Kh;                 // alias
    __nv_bfloat16* Pl = Kl;

    const int h     = blockIdx.x;
    const int qb    = blockIdx.y;
    const int tid   = threadIdx.x;
    const int warp  = tid >> 5;
    const int qbase = qb * 64;
    const int rt    = warp >> 1;           // row tile 0..3 (rows rt*16..+15)
    const int chalf = (warp & 1) * 32;     // col half

    // ---- stage Q (scaled 0.125, hi/lo) via Kh/Kl, load frags to registers
    #pragma unroll
    for (int it = 0; it < 16; it++) {
        int idx = tid + it * 256;
        int row = idx >> 6, col = idx & 63;
        float v = qkv[(long)(qbase + row) * (3 * DMOD) + h * HDIM + col] * 0.125f;
        __nv_bfloat16 hi = __float2bfloat16(v);
        Kh[row * BSTR + col] = hi;
        Kl[row * BSTR + col] = __float2bfloat16(v - __bfloat162float(hi));
    }
    __syncthreads();
    wmma::fragment<wmma::matrix_a, 16, 16, 16, __nv_bfloat16, wmma::row_major> qh[4], ql[4];
    #pragma unroll
    for (int ks = 0; ks < 4; ks++) {
        wmma::load_matrix_sync(qh[ks], Kh + rt * 16 * BSTR + ks * 16, BSTR);
        wmma::load_matrix_sync(ql[ks], Kl + rt * 16 * BSTR + ks * 16, BSTR);
    }
    // zero O
    #pragma unroll
    for (int it = 0; it < 16; it++) {
        int idx = tid + it * 256;
        Of[(idx >> 6) * FSTR + (idx & 63)] = 0.f;
    }
    __syncthreads();

    const int r  = tid >> 2;           // row owned by this thread
    const int cs = (tid & 3) * 16;     // col segment
    float mrow = -1e30f, lsum = 0.f, alpha = 0.f;

    for (int kb = 0; kb <= qb; kb++) {
        const int kbase = kb * 64;

        // ---- load K,V (fp32 -> hi/lo bf16)
        #pragma unroll
        for (int it = 0; it < 16; it++) {
            int idx = tid + it * 256;
            int row = idx >> 6, col = idx & 63;
            long base = (long)(kbase + row) * (3 * DMOD) + h * HDIM + col;
            float kv = qkv[base + DMOD];
            float vv = qkv[base + 2 * DMOD];
            __nv_bfloat16 khi = __float2bfloat16(kv);
            Kh[row * BSTR + col] = khi;
            Kl[row * BSTR + col] = __float2bfloat16(kv - __bfloat162float(khi));
            __nv_bfloat16 vhi = __float2bfloat16(vv);
            Vh[row * BSTR + col] = vhi;
            Vl[row * BSTR + col] = __float2bfloat16(vv - __bfloat162float(vhi));
        }
        __syncthreads();

        // ---- S = Q K^T (split, 3 passes), store fp32 to Sf
        #pragma unroll
        for (int ct = 0; ct < 2; ct++) {
            const int col0 = chalf + ct * 16;
            wmma::fragment<wmma::accumulator, 16, 16, 16, float> acc;
            wmma::fill_fragment(acc, 0.f);
            #pragma unroll
            for (int ks = 0; ks < 4; ks++) {
                wmma::fragment<wmma::matrix_b, 16, 16, 16, __nv_bfloat16,
                               wmma::col_major> bh, bl;
                wmma::load_matrix_sync(bh, Kh + col0 * BSTR + ks * 16, BSTR);
                wmma::load_matrix_sync(bl, Kl + col0 * BSTR + ks * 16, BSTR);
                wmma::mma_sync(acc, qh[ks], bl, acc);
                wmma::mma_sync(acc, ql[ks], bh, acc);
                wmma::mma_sync(acc, qh[ks], bh, acc);
            }
            wmma::store_matrix_sync(Sf + rt * 16 * FSTR + col0, acc, FSTR,
                                    wmma::mem_row_major);
        }
        __syncthreads();

        // ---- online softmax on row r (4 threads per row)
        float s[16];
        #pragma unroll
        for (int j = 0; j < 16; j++) s[j] = Sf[r * FSTR + cs + j];
        if (kb == qb) {
            #pragma unroll
            for (int j = 0; j < 16; j++)
                if (kbase + cs + j > qbase + r) s[j] = -1e30f;
        }
        float mloc = s[0];
        #pragma unroll
        for (int j = 1; j < 16; j++) mloc = fmaxf(mloc, s[j]);
        mloc = fmaxf(mloc, __shfl_xor_sync(0xffffffffu, mloc, 1));
        mloc = fmaxf(mloc, __shfl_xor_sync(0xffffffffu, mloc, 2));
        const float mnew = fmaxf(mrow, mloc);
        alpha = __expf(mrow - mnew);

        float ps = 0.f;
        #pragma unroll
        for (int j = 0; j < 16; j++) {
            float p = __expf(s[j] - mnew);
            ps += p;
            __nv_bfloat16 phi = __float2bfloat16(p);
            Ph[r * BSTR + cs + j] = phi;
            Pl[r * BSTR + cs + j] = __float2bfloat16(p - __bfloat162float(phi));
        }
        ps += __shfl_xor_sync(0xffffffffu, ps, 1);
        ps += __shfl_xor_sync(0xffffffffu, ps, 2);
        lsum = lsum * alpha + ps;
        mrow = mnew;
        __syncthreads();

        // ---- T = P V (split, 3 passes), store into Sf
        #pragma unroll
        for (int ct = 0; ct < 2; ct++) {
            const int col0 = chalf + ct * 16;
            wmma::fragment<wmma::accumulator, 16, 16, 16, float> acc;
            wmma::fill_fragment(acc, 0.f);
            #pragma unroll
            for (int js = 0; js < 4; js++) {
                wmma::fragment<wmma::matrix_a, 16, 16, 16, __nv_bfloat16,
                               wmma::row_major> ph, pl;
                wmma::load_matrix_sync(ph, Ph + rt * 16 * BSTR + js * 16, BSTR);
                wmma::load_matrix_sync(pl, Pl + rt * 16 * BSTR + js * 16, BSTR);
                wmma::fragment<wmma::matrix_b, 16, 16, 16, __nv_bfloat16,
                               wmma::row_major> vh, vl;
                wmma::load_matrix_sync(vh, Vh + js * 16 * BSTR + col0, BSTR);
                wmma::load_matrix_sync(vl, Vl + js * 16 * BSTR + col0, BSTR);
                wmma::mma_sync(acc, ph, vl, acc);
                wmma::mma_sync(acc, pl, vh, acc);
                wmma::mma_sync(acc, ph, vh, acc);
            }
            wmma::store_matrix_sync(Sf + rt * 16 * FSTR + col0, acc, FSTR,
                                    wmma::mem_row_major);
        }
        __syncthreads();

        // ---- O = alpha*O + T
        #pragma unroll
        for (int j = 0; j < 16; j++) {
            int o = r * FSTR + cs + j;
            Of[o] = Of[o] * alpha + Sf[o];
        }
        __syncthreads();
    }

    const float invl = 1.f / lsum;
    float* orow = out + (long)(qbase + r) * DMOD + h * HDIM + cs;
    #pragma unroll
    for (int j = 0; j < 16; j++) orow[j] = Of[r * FSTR + cs + j] * invl;
}

// ---------------- SwiGLU ------------------------------------------------------
__global__ void swiglu_kernel(const float* __restrict__ g,
                              float* __restrict__ out) {
    const int idx = blockIdx.x * 256 + threadIdx.x;
    if (idx >= SEQ * (DMLP / 2)) return;
    const int rw = idx >> 12;
    const int c  = idx & 4095;
    const float x1 = g[(long)rw * DMLP + c];
    const float x2 = g[(long)rw * DMLP + (DMLP / 2) + c];
    const float sig = 1.f / (1.f + __expf(-x2));
    out[idx] = x2 * sig * x1;
}

// ---------------- launch ------------------------------------------------------
extern "C" void kernel_launch(void* const* d_in, const int* in_sizes, int n_in,
                              void* d_out, int out_size) {
    const float* x      = (const float*)d_in[0];
    const float* W_attn = (const float*)d_in[2];
    const float* W_out  = (const float*)d_in[3];
    const float* W_ffp  = (const float*)d_in[4];
    const float* W_ffo  = (const float*)d_in[5];
    float* out = (float*)d_out;

    float *xn, *qkv, *attn, *h, *hn, *gbuf, *mlp;
    cudaGetSymbolAddress((void**)&xn,   g_xn);
    cudaGetSymbolAddress((void**)&qkv,  g_qkv);
    cudaGetSymbolAddress((void**)&attn, g_attn);
    cudaGetSymbolAddress((void**)&h,    g_h);
    cudaGetSymbolAddress((void**)&hn,   g_hn);
    cudaGetSymbolAddress((void**)&gbuf, g_g);
    cudaGetSymbolAddress((void**)&mlp,  g_mlp);

    cudaFuncSetAttribute(attn_wmma,
                         cudaFuncAttributeMaxDynamicSharedMemorySize, ATW_SMEM);

    ln_kernel<<<SEQ, 256>>>(x, xn);

    gemm_bf16x3<<<dim3(3 * DMOD / GBN, SEQ / GBM), 256>>>(
        xn, DMOD, W_attn, DMOD, qkv, 3 * DMOD, nullptr, DMOD);

    rope_kernel<<<(SEQ * NHEAD * 32 + 255) / 256, 256>>>(qkv);

    attn_wmma<<<dim3(NHEAD, SEQ / 64), 256, ATW_SMEM>>>(qkv, attn);

    gemm_bf16x3<<<dim3(DMOD / GBN, SEQ / GBM), 256>>>(
        attn, DMOD, W_out, DMOD, h, DMOD, x, DMOD);

    ln_kernel<<<SEQ, 256>>>(h, hn);

    gemm_bf16x3<<<dim3(DMLP / GBN, SEQ / GBM), 256>>>(
        hn, DMOD, W_ffp, DMOD, gbuf, DMLP, nullptr, DMOD);

    swiglu_kernel<<<(SEQ * (DMLP / 2) + 255) / 256, 256>>>(gbuf, mlp);

    gemm_bf16x3<<<dim3(DMOD / GBN, SEQ / GBM), 256>>>(
        mlp, DMLP / 2, W_ffo, DMLP / 2, out, DMOD, h, DMLP / 2);
}

// round 6
// speedup vs baseline: 3.8072x; 1.5350x over previous
#include <cuda_runtime.h>
#include <cuda_bf16.h>
#include <mma.h>
#include <math.h>
#include <cstdint>

using namespace nvcuda;
typedef __nv_bfloat16 bf16;

#define SEQ   2048
#define DMOD  1024
#define NHEAD 16
#define HDIM  64
#define DMLP  8192

// ---------------- scratch -----------------------------------------------------
__device__ float g_qkv[SEQ * 3 * DMOD];
__device__ float g_h  [SEQ * DMOD];
__device__ float g_g  [SEQ * DMLP];
__device__ bf16  g_xnh[SEQ * DMOD],      g_xnl[SEQ * DMOD];
__device__ bf16  g_ath[SEQ * DMOD],      g_atl[SEQ * DMOD];
__device__ bf16  g_hnh[SEQ * DMOD],      g_hnl[SEQ * DMOD];
__device__ bf16  g_mph[SEQ * DMLP / 2],  g_mpl[SEQ * DMLP / 2];
__device__ bf16  g_Wah[3 * DMOD * DMOD], g_Wal[3 * DMOD * DMOD];
__device__ bf16  g_Woh[DMOD * DMOD],     g_Wol[DMOD * DMOD];
__device__ bf16  g_Wph[DMLP * DMOD],     g_Wpl[DMLP * DMOD];
__device__ bf16  g_Wfh[DMOD * DMLP / 2], g_Wfl[DMOD * DMLP / 2];

__device__ __forceinline__ void split_hl(float v, bf16& h, bf16& l) {
    h = __float2bfloat16(v);
    l = __float2bfloat16(v - __bfloat162float(h));
}

// ---------------- weight fp32 -> bf16 hi/lo -----------------------------------
__global__ void __launch_bounds__(256) cvt_hilo(const float* __restrict__ s,
                                                bf16* __restrict__ h,
                                                bf16* __restrict__ l, int n) {
    int i = (blockIdx.x * 256 + threadIdx.x) * 4;
    if (i >= n) return;
    float4 v = *(const float4*)(s + i);
    float a[4] = {v.x, v.y, v.z, v.w};
    #pragma unroll
    for (int e = 0; e < 4; e++) split_hl(a[e], h[i + e], l[i + e]);
}

// ---------------- LayerNorm -> bf16 hi/lo -------------------------------------
__global__ void __launch_bounds__(256) ln_kernel(const float* __restrict__ x,
                                                 bf16* __restrict__ yh,
                                                 bf16* __restrict__ yl) {
    __shared__ float row[DMOD];
    __shared__ float red[256];
    const int r   = blockIdx.x;
    const int tid = threadIdx.x;
    const float* xr = x + (long)r * DMOD;

    float s = 0.f;
    #pragma unroll
    for (int i = 0; i < 4; i++) {
        float v = xr[tid + i * 256];
        row[tid + i * 256] = v;
        s += v;
    }
    red[tid] = s; __syncthreads();
    #pragma unroll
    for (int off = 128; off > 0; off >>= 1) {
        if (tid < off) red[tid] += red[tid + off];
        __syncthreads();
    }
    const float mu = red[0] * (1.f / DMOD);
    __syncthreads();

    float ss = 0.f;
    #pragma unroll
    for (int i = 0; i < 4; i++) {
        float d = row[tid + i * 256] - mu;
        ss += d * d;
    }
    red[tid] = ss; __syncthreads();
    #pragma unroll
    for (int off = 128; off > 0; off >>= 1) {
        if (tid < off) red[tid] += red[tid + off];
        __syncthreads();
    }
    const float inv = rsqrtf(red[0] * (1.f / DMOD) + 1e-5f);

    #pragma unroll
    for (int i = 0; i < 4; i++) {
        int c = tid + i * 256;
        split_hl((row[c] - mu) * inv, yh[(long)r * DMOD + c], yl[(long)r * DMOD + c]);
    }
}

// ---------------- pipelined tensor-core GEMM (pre-split bf16 inputs) ----------
// C[M,N](fp32) = (Ah+Al)[M,K] * (Bh+Bl)[N,K]^T (+Res), 3-pass split mma.
// 128x128 tile, BK=32, 256 threads, 2-stage cp.async double buffer.
#define GBK   32
#define PADK  40
#define GEMM_SMEM (2 * 4 * 128 * PADK * (int)sizeof(bf16))   // 81920 B

__device__ __forceinline__ void cp16(bf16* dst, const bf16* src) {
    uint32_t s = (uint32_t)__cvta_generic_to_shared(dst);
    asm volatile("cp.async.cg.shared.global [%0], [%1], 16;\n" :: "r"(s), "l"(src));
}

__global__ void __launch_bounds__(256, 2) gemm_pre(
    const bf16* __restrict__ Ah, const bf16* __restrict__ Al, int lda,
    const bf16* __restrict__ Bh, const bf16* __restrict__ Bl, int ldb,
    float* __restrict__ C, int ldc, const float* __restrict__ Res, int K)
{
    extern __shared__ bf16 sm[];
    const int tid  = threadIdx.x;
    const int m0   = blockIdx.y * 128;
    const int n0   = blockIdx.x * 128;
    const int warp = tid >> 5;
    const int wm0  = (warp & 3) * 32;
    const int wn0  = (warp >> 2) * 64;

    wmma::fragment<wmma::accumulator, 16, 16, 16, float> acc[2][4];
    #pragma unroll
    for (int i = 0; i < 2; i++)
        #pragma unroll
        for (int j = 0; j < 4; j++) {
            if (Res) {
                const float* rp = Res + (long)(m0 + wm0 + 16 * i) * ldc
                                      + n0 + wn0 + 16 * j;
                wmma::load_matrix_sync(acc[i][j], rp, ldc, wmma::mem_row_major);
            } else {
                wmma::fill_fragment(acc[i][j], 0.f);
            }
        }

    const bf16* base0 = Ah + (long)m0 * lda;
    const bf16* base1 = Al + (long)m0 * lda;
    const bf16* base2 = Bh + (long)n0 * ldb;
    const bf16* base3 = Bl + (long)n0 * ldb;

    // one stage = 4 arrays x 128 rows x 32 bf16 = 2048 x 16B chunks; 8/thread
    #define LOAD_STAGE(ST, K0)                                                 \
    do {                                                                       \
        bf16* sb = sm + (ST) * (4 * 128 * PADK);                               \
        _Pragma("unroll")                                                      \
        for (int t = 0; t < 8; t++) {                                          \
            int c   = tid + t * 256;                                           \
            int arr = c >> 9;                                                  \
            int rem = c & 511;                                                 \
            int row = rem >> 2;                                                \
            int col = (rem & 3) * 8;                                           \
            const bf16* src =                                                  \
                (arr == 0) ? base0 + (long)row * lda + (K0) + col :            \
                (arr == 1) ? base1 + (long)row * lda + (K0) + col :            \
                (arr == 2) ? base2 + (long)row * ldb + (K0) + col :            \
                             base3 + (long)row * ldb + (K0) + col;             \
            cp16(sb + arr * (128 * PADK) + row * PADK + col, src);             \
        }                                                                      \
    } while (0)

    const int nk = K / GBK;
    LOAD_STAGE(0, 0);
    asm volatile("cp.async.commit_group;\n" ::);

    for (int ks = 0; ks < nk; ks++) {
        asm volatile("cp.async.wait_group 0;\n" ::);
        __syncthreads();
        if (ks + 1 < nk) {
            LOAD_STAGE((ks + 1) & 1, (ks + 1) * GBK);
            asm volatile("cp.async.commit_group;\n" ::);
        }
        bf16* sb  = sm + (ks & 1) * (4 * 128 * PADK);
        bf16* sAh = sb;
        bf16* sAl = sb + 128 * PADK;
        bf16* sBh = sb + 2 * 128 * PADK;
        bf16* sBl = sb + 3 * 128 * PADK;

        #pragma unroll
        for (int k16 = 0; k16 < GBK; k16 += 16) {
            wmma::fragment<wmma::matrix_a, 16, 16, 16, bf16, wmma::row_major> ah[2], al[2];
            #pragma unroll
            for (int i = 0; i < 2; i++) {
                wmma::load_matrix_sync(ah[i], sAh + (wm0 + 16 * i) * PADK + k16, PADK);
                wmma::load_matrix_sync(al[i], sAl + (wm0 + 16 * i) * PADK + k16, PADK);
            }
            #pragma unroll
            for (int j = 0; j < 4; j++) {
                wmma::fragment<wmma::matrix_b, 16, 16, 16, bf16, wmma::col_major> bh, bl;
                wmma::load_matrix_sync(bh, sBh + (wn0 + 16 * j) * PADK + k16, PADK);
                wmma::load_matrix_sync(bl, sBl + (wn0 + 16 * j) * PADK + k16, PADK);
                #pragma unroll
                for (int i = 0; i < 2; i++) {
                    wmma::mma_sync(acc[i][j], ah[i], bl, acc[i][j]);
                    wmma::mma_sync(acc[i][j], al[i], bh, acc[i][j]);
                    wmma::mma_sync(acc[i][j], ah[i], bh, acc[i][j]);
                }
            }
        }
    }

    #pragma unroll
    for (int i = 0; i < 2; i++)
        #pragma unroll
        for (int j = 0; j < 4; j++) {
            float* cp = C + (long)(m0 + wm0 + 16 * i) * ldc + n0 + wn0 + 16 * j;
            wmma::store_matrix_sync(cp, acc[i][j], ldc, wmma::mem_row_major);
        }
}

// ---------------- RoPE --------------------------------------------------------
__global__ void rope_kernel(float* __restrict__ qkv) {
    const int idx = blockIdx.x * 256 + threadIdx.x;
    if (idx >= SEQ * NHEAD * 32) return;
    const int j = idx & 31;
    const int h = (idx >> 5) & (NHEAD - 1);
    const int l = idx >> 9;

    const float inv_freq = powf(10000.f, -(float)j / 32.f);
    const float ang = (float)l * inv_freq;
    float c, s;
    sincosf(ang, &s, &c);

    float* qp = qkv + (long)l * (3 * DMOD) + h * HDIM + j;
    float q1 = qp[0], q2 = qp[32];
    qp[0]  = q1 * c - q2 * s;
    qp[32] = q2 * c + q1 * s;

    float* kp = qp + DMOD;
    float k1 = kp[0], k2 = kp[32];
    kp[0]  = k1 * c - k2 * s;
    kp[32] = k2 * c + k1 * s;
}

// ---------------- Flash attention on tensor cores (hi/lo output) --------------
#define BSTR 72
#define FSTR 68
#define ATW_SMEM (4 * 64 * BSTR * 2 + 2 * 64 * FSTR * 4)

__global__ void __launch_bounds__(256, 2) attn_wmma(const float* __restrict__ qkv,
                                                    bf16* __restrict__ outh,
                                                    bf16* __restrict__ outl) {
    extern __shared__ char smraw[];
    bf16* Kh = (bf16*)smraw;
    bf16* Kl = Kh + 64 * BSTR;
    bf16* Vh = Kl + 64 * BSTR;
    bf16* Vl = Vh + 64 * BSTR;
    float* Sf = (float*)(Vl + 64 * BSTR);
    float* Of = Sf + 64 * FSTR;
    bf16* Ph = Kh;
    bf16* Pl = Kl;

    const int h     = blockIdx.x;
    const int qb    = blockIdx.y;
    const int tid   = threadIdx.x;
    const int warp  = tid >> 5;
    const int qbase = qb * 64;
    const int rt    = warp >> 1;
    const int chalf = (warp & 1) * 32;

    #pragma unroll
    for (int it = 0; it < 16; it++) {
        int idx = tid + it * 256;
        int row = idx >> 6, col = idx & 63;
        float v = qkv[(long)(qbase + row) * (3 * DMOD) + h * HDIM + col] * 0.125f;
        split_hl(v, Kh[row * BSTR + col], Kl[row * BSTR + col]);
    }
    __syncthreads();
    wmma::fragment<wmma::matrix_a, 16, 16, 16, bf16, wmma::row_major> qh[4], ql[4];
    #pragma unroll
    for (int ks = 0; ks < 4; ks++) {
        wmma::load_matrix_sync(qh[ks], Kh + rt * 16 * BSTR + ks * 16, BSTR);
        wmma::load_matrix_sync(ql[ks], Kl + rt * 16 * BSTR + ks * 16, BSTR);
    }
    #pragma unroll
    for (int it = 0; it < 16; it++) {
        int idx = tid + it * 256;
        Of[(idx >> 6) * FSTR + (idx & 63)] = 0.f;
    }
    __syncthreads();

    const int r  = tid >> 2;
    const int cs = (tid & 3) * 16;
    float mrow = -1e30f, lsum = 0.f, alpha = 0.f;

    for (int kb = 0; kb <= qb; kb++) {
        const int kbase = kb * 64;

        #pragma unroll
        for (int it = 0; it < 16; it++) {
            int idx = tid + it * 256;
            int row = idx >> 6, col = idx & 63;
            long base = (long)(kbase + row) * (3 * DMOD) + h * HDIM + col;
            split_hl(qkv[base + DMOD],     Kh[row * BSTR + col], Kl[row * BSTR + col]);
            split_hl(qkv[base + 2 * DMOD], Vh[row * BSTR + col], Vl[row * BSTR + col]);
        }
        __syncthreads();

        #pragma unroll
        for (int ct = 0; ct < 2; ct++) {
            const int col0 = chalf + ct * 16;
            wmma::fragment<wmma::accumulator, 16, 16, 16, float> acc;
            wmma::fill_fragment(acc, 0.f);
            #pragma unroll
            for (int ks = 0; ks < 4; ks++) {
                wmma::fragment<wmma::matrix_b, 16, 16, 16, bf16, wmma::col_major> bh, bl;
                wmma::load_matrix_sync(bh, Kh + col0 * BSTR + ks * 16, BSTR);
                wmma::load_matrix_sync(bl, Kl + col0 * BSTR + ks * 16, BSTR);
                wmma::mma_sync(acc, qh[ks], bl, acc);
                wmma::mma_sync(acc, ql[ks], bh, acc);
                wmma::mma_sync(acc, qh[ks], bh, acc);
            }
            wmma::store_matrix_sync(Sf + rt * 16 * FSTR + col0, acc, FSTR,
                                    wmma::mem_row_major);
        }
        __syncthreads();

        float s[16];
        #pragma unroll
        for (int j = 0; j < 16; j++) s[j] = Sf[r * FSTR + cs + j];
        if (kb == qb) {
            #pragma unroll
            for (int j = 0; j < 16; j++)
                if (kbase + cs + j > qbase + r) s[j] = -1e30f;
        }
        float mloc = s[0];
        #pragma unroll
        for (int j = 1; j < 16; j++) mloc = fmaxf(mloc, s[j]);
        mloc = fmaxf(mloc, __shfl_xor_sync(0xffffffffu, mloc, 1));
        mloc = fmaxf(mloc, __shfl_xor_sync(0xffffffffu, mloc, 2));
        const float mnew = fmaxf(mrow, mloc);
        alpha = __expf(mrow - mnew);

        float ps = 0.f;
        #pragma unroll
        for (int j = 0; j < 16; j++) {
            float p = __expf(s[j] - mnew);
            ps += p;
            split_hl(p, Ph[r * BSTR + cs + j], Pl[r * BSTR + cs + j]);
        }
        ps += __shfl_xor_sync(0xffffffffu, ps, 1);
        ps += __shfl_xor_sync(0xffffffffu, ps, 2);
        lsum = lsum * alpha + ps;
        mrow = mnew;
        __syncthreads();

        #pragma unroll
        for (int ct = 0; ct < 2; ct++) {
            const int col0 = chalf + ct * 16;
            wmma::fragment<wmma::accumulator, 16, 16, 16, float> acc;
            wmma::fill_fragment(acc, 0.f);
            #pragma unroll
            for (int js = 0; js < 4; js++) {
                wmma::fragment<wmma::matrix_a, 16, 16, 16, bf16, wmma::row_major> ph, pl;
                wmma::load_matrix_sync(ph, Ph + rt * 16 * BSTR + js * 16, BSTR);
                wmma::load_matrix_sync(pl, Pl + rt * 16 * BSTR + js * 16, BSTR);
                wmma::fragment<wmma::matrix_b, 16, 16, 16, bf16, wmma::row_major> vh, vl;
                wmma::load_matrix_sync(vh, Vh + js * 16 * BSTR + col0, BSTR);
                wmma::load_matrix_sync(vl, Vl + js * 16 * BSTR + col0, BSTR);
                wmma::mma_sync(acc, ph, vl, acc);
                wmma::mma_sync(acc, pl, vh, acc);
                wmma::mma_sync(acc, ph, vh, acc);
            }
            wmma::store_matrix_sync(Sf + rt * 16 * FSTR + col0, acc, FSTR,
                                    wmma::mem_row_major);
        }
        __syncthreads();

        #pragma unroll
        for (int j = 0; j < 16; j++) {
            int o = r * FSTR + cs + j;
            Of[o] = Of[o] * alpha + Sf[o];
        }
        __syncthreads();
    }

    const float invl = 1.f / lsum;
    long obase = (long)(qbase + r) * DMOD + h * HDIM + cs;
    #pragma unroll
    for (int j = 0; j < 16; j++)
        split_hl(Of[r * FSTR + cs + j] * invl, outh[obase + j], outl[obase + j]);
}

// ---------------- SwiGLU -> bf16 hi/lo -----------------------------------------
__global__ void __launch_bounds__(256) swiglu_kernel(const float* __restrict__ g,
                                                     bf16* __restrict__ oh,
                                                     bf16* __restrict__ ol) {
    const int idx = blockIdx.x * 256 + threadIdx.x;
    if (idx >= SEQ * (DMLP / 2)) return;
    const int rw = idx >> 12;
    const int c  = idx & 4095;
    const float x1 = g[(long)rw * DMLP + c];
    const float x2 = g[(long)rw * DMLP + (DMLP / 2) + c];
    const float sig = 1.f / (1.f + __expf(-x2));
    split_hl(x2 * sig * x1, oh[idx], ol[idx]);
}

// ---------------- launch --------------------------------------------------------
extern "C" void kernel_launch(void* const* d_in, const int* in_sizes, int n_in,
                              void* d_out, int out_size) {
    const float* x      = (const float*)d_in[0];
    const float* W_attn = (const float*)d_in[2];
    const float* W_out  = (const float*)d_in[3];
    const float* W_ffp  = (const float*)d_in[4];
    const float* W_ffo  = (const float*)d_in[5];
    float* out = (float*)d_out;

    float *qkv, *h, *gbuf;
    bf16 *xnh, *xnl, *ath, *atl, *hnh, *hnl, *mph, *mpl;
    bf16 *Wah, *Wal, *Woh, *Wol, *Wph, *Wpl, *Wfh, *Wfl;
    cudaGetSymbolAddress((void**)&qkv, g_qkv);
    cudaGetSymbolAddress((void**)&h,   g_h);
    cudaGetSymbolAddress((void**)&gbuf,g_g);
    cudaGetSymbolAddress((void**)&xnh, g_xnh); cudaGetSymbolAddress((void**)&xnl, g_xnl);
    cudaGetSymbolAddress((void**)&ath, g_ath); cudaGetSymbolAddress((void**)&atl, g_atl);
    cudaGetSymbolAddress((void**)&hnh, g_hnh); cudaGetSymbolAddress((void**)&hnl, g_hnl);
    cudaGetSymbolAddress((void**)&mph, g_mph); cudaGetSymbolAddress((void**)&mpl, g_mpl);
    cudaGetSymbolAddress((void**)&Wah, g_Wah); cudaGetSymbolAddress((void**)&Wal, g_Wal);
    cudaGetSymbolAddress((void**)&Woh, g_Woh); cudaGetSymbolAddress((void**)&Wol, g_Wol);
    cudaGetSymbolAddress((void**)&Wph, g_Wph); cudaGetSymbolAddress((void**)&Wpl, g_Wpl);
    cudaGetSymbolAddress((void**)&Wfh, g_Wfh); cudaGetSymbolAddress((void**)&Wfl, g_Wfl);

    cudaFuncSetAttribute(attn_wmma,
                         cudaFuncAttributeMaxDynamicSharedMemorySize, ATW_SMEM);
    cudaFuncSetAttribute(gemm_pre,
                         cudaFuncAttributeMaxDynamicSharedMemorySize, GEMM_SMEM);

    // weight splits (independent of activations)
    { int n = 3 * DMOD * DMOD; cvt_hilo<<<n / 4 / 256, 256>>>(W_attn, Wah, Wal, n); }
    { int n = DMOD * DMOD;     cvt_hilo<<<n / 4 / 256, 256>>>(W_out,  Woh, Wol, n); }
    { int n = DMLP * DMOD;     cvt_hilo<<<n / 4 / 256, 256>>>(W_ffp,  Wph, Wpl, n); }
    { int n = DMOD * DMLP / 2; cvt_hilo<<<n / 4 / 256, 256>>>(W_ffo,  Wfh, Wfl, n); }

    // 1) xn = LN(x) -> hi/lo
    ln_kernel<<<SEQ, 256>>>(x, xnh, xnl);

    // 2) qkv = xn @ W_attn^T
    gemm_pre<<<dim3(3 * DMOD / 128, SEQ / 128), 256, GEMM_SMEM>>>(
        xnh, xnl, DMOD, Wah, Wal, DMOD, qkv, 3 * DMOD, nullptr, DMOD);

    // 3) RoPE
    rope_kernel<<<(SEQ * NHEAD * 32 + 255) / 256, 256>>>(qkv);

    // 4) attention -> hi/lo
    attn_wmma<<<dim3(NHEAD, SEQ / 64), 256, ATW_SMEM>>>(qkv, ath, atl);

    // 5) h = attn @ W_out^T + x
    gemm_pre<<<dim3(DMOD / 128, SEQ / 128), 256, GEMM_SMEM>>>(
        ath, atl, DMOD, Woh, Wol, DMOD, h, DMOD, x, DMOD);

    // 6) hn = LN(h) -> hi/lo
    ln_kernel<<<SEQ, 256>>>(h, hnh, hnl);

    // 7) g = hn @ W_ffp^T
    gemm_pre<<<dim3(DMLP / 128, SEQ / 128), 256, GEMM_SMEM>>>(
        hnh, hnl, DMOD, Wph, Wpl, DMOD, gbuf, DMLP, nullptr, DMOD);

    // 8) mlp = silu(g2)*g1 -> hi/lo
    swiglu_kernel<<<(SEQ * (DMLP / 2) + 255) / 256, 256>>>(gbuf, mph, mpl);

    // 9) out = mlp @ W_ffo^T + h
    gemm_pre<<<dim3(DMOD / 128, SEQ / 128), 256, GEMM_SMEM>>>(
        mph, mpl, DMLP / 2, Wfh, Wfl, DMLP / 2, out, DMOD, h, DMLP / 2);
}